// round 2
// baseline (speedup 1.0000x reference)
#include <cuda_runtime.h>
#include <cstddef>

#define NDIM 768
#define CDIM 128
#define NN ((size_t)NDIM * (size_t)NDIM)

// Scratch (allocation-free rule: __device__ globals).
// Layouts:
//   g_a, g_b : (C, N, N)  -> per-channel 768x768 matrices, k contiguous (NT GEMM operands)
//   g_g      : (N*N, C)   -> sigmoid(x @ gating_w.T), pixel-major for the final epilogue
//   g_t      : (C, N, N)  -> einsum result, channel-major
__device__ float g_a[(size_t)CDIM * NDIM * NDIM];
__device__ float g_b[(size_t)CDIM * NDIM * NDIM];
__device__ float g_g[(size_t)NDIM * NDIM * CDIM];
__device__ float g_t[(size_t)CDIM * NDIM * NDIM];

__device__ __forceinline__ float sigf(float x) {
    return 1.0f / (1.0f + __expf(-x));
}

// ---------------------------------------------------------------------------
// Kernel A: LN1 + [proj|gate|gating] GEMM + sigmoid/mask epilogue.
// Block: 64 pixels (rows) x 16 channels (=80 GEMM outputs, 5 per channel).
// Weight rows are gathered in interleaved order so the epilogue is local:
//   o = 5*cl + r : r0=proj[2c], r1=gate[2c], r2=proj[2c+1], r3=gate[2c+1], r4=gating[c]
// ---------------------------------------------------------------------------
__global__ __launch_bounds__(256) void kA(
    const float* __restrict__ pair, const float* __restrict__ mask,
    const float* __restrict__ ln1w, const float* __restrict__ ln1b,
    const float* __restrict__ projw, const float* __restrict__ gatew,
    const float* __restrict__ gatingw)
{
    __shared__ float Xs[64][132];   // 64 pixels x 128 channels (LN'd), padded
    __shared__ float Ws[32][81];    // k-chunk x 80 outputs, pad 81 (odd -> conflict-free)

    const int t = threadIdx.x;
    const size_t P0 = (size_t)blockIdx.x * 64;
    const float* src = pair + P0 * CDIM;

    // Coalesced tile load
    #pragma unroll
    for (int i = 0; i < 8; i++) {
        int idx = i * 1024 + t * 4;
        int p = idx >> 7, k = idx & 127;
        float4 v = *(const float4*)(src + idx);
        *(float4*)&Xs[p][k] = v;
    }
    __syncthreads();

    // LayerNorm: 4 threads per pixel row, quad shuffle reduce
    {
        const int row = t >> 2, quad = t & 3;
        const int k0 = quad * 32;
        float s = 0.f;
        #pragma unroll
        for (int k = 0; k < 32; k++) s += Xs[row][k0 + k];
        s += __shfl_xor_sync(0xffffffffu, s, 1);
        s += __shfl_xor_sync(0xffffffffu, s, 2);
        const float mu = s * (1.0f / 128.0f);
        float vv = 0.f;
        #pragma unroll
        for (int k = 0; k < 32; k++) { float d = Xs[row][k0 + k] - mu; vv += d * d; }
        vv += __shfl_xor_sync(0xffffffffu, vv, 1);
        vv += __shfl_xor_sync(0xffffffffu, vv, 2);
        const float inv = rsqrtf(vv * (1.0f / 128.0f) + 1e-5f);
        #pragma unroll
        for (int k = 0; k < 32; k++) {
            int kk = k0 + k;
            Xs[row][kk] = (Xs[row][kk] - mu) * inv * ln1w[kk] + ln1b[kk];
        }
    }
    __syncthreads();

    const int tx = t & 15;          // channel within tile
    const int ty = t >> 4;          // pixel group (4 pixels each)
    const int cbase = blockIdx.y * 16;
    const int wid = t >> 5, lane = t & 31;

    float acc[4][5];
    #pragma unroll
    for (int r = 0; r < 4; r++)
        #pragma unroll
        for (int j = 0; j < 5; j++) acc[r][j] = 0.f;

    for (int kc = 0; kc < 4; kc++) {
        __syncthreads();
        // Each warp loads one W row per iteration (warp-uniform row pointer)
        #pragma unroll
        for (int i = 0; i < 10; i++) {
            int o = i * 8 + wid;
            int cl = o / 5, r = o % 5;
            int c = cbase + cl;
            const float* rp;
            if (r == 0)      rp = projw   + (size_t)(2 * c) * CDIM;
            else if (r == 1) rp = gatew   + (size_t)(2 * c) * CDIM;
            else if (r == 2) rp = projw   + (size_t)(2 * c + 1) * CDIM;
            else if (r == 3) rp = gatew   + (size_t)(2 * c + 1) * CDIM;
            else             rp = gatingw + (size_t)c * CDIM;
            Ws[lane][o] = rp[kc * 32 + lane];
        }
        __syncthreads();

        #pragma unroll
        for (int kk = 0; kk < 32; kk++) {
            const int k = kc * 32 + kk;
            float xv[4];
            #pragma unroll
            for (int r = 0; r < 4; r++) xv[r] = Xs[ty * 4 + r][k];
            float wv[5];
            #pragma unroll
            for (int j = 0; j < 5; j++) wv[j] = Ws[kk][tx * 5 + j];
            #pragma unroll
            for (int r = 0; r < 4; r++)
                #pragma unroll
                for (int j = 0; j < 5; j++)
                    acc[r][j] += xv[r] * wv[j];
        }
    }

    // Epilogue: a = proj_e*sig(gate_e)*mask[k], b = proj_o*sig(gate_o)*mask[k], g = sig(gating)
    const int c = cbase + tx;
    #pragma unroll
    for (int r = 0; r < 4; r++) {
        size_t P = P0 + (size_t)(ty * 4 + r);
        int kcol = (int)(P % NDIM);
        float m = mask[kcol];
        float av = acc[r][0] * sigf(acc[r][1]) * m;
        float bv = acc[r][2] * sigf(acc[r][3]) * m;
        float gv = sigf(acc[r][4]);
        g_a[(size_t)c * NN + P] = av;
        g_b[(size_t)c * NN + P] = bv;
        g_g[P * CDIM + c] = gv;
    }
}

// ---------------------------------------------------------------------------
// Kernel B: batched NT SGEMM. For each channel c:
//   out_c[i][j] = sum_k a_c[i][k] * b_c[j][k]
// Tiles 128x128x32, 256 threads, 8x8 register tiles.
// ---------------------------------------------------------------------------
__global__ __launch_bounds__(256) void kB()
{
    __shared__ float As[32][132];
    __shared__ float Bs[32][132];

    const int t = threadIdx.x;
    const int tx = t & 15, ty = t >> 4;
    const int c = blockIdx.z;

    const float* Ag = g_a + (size_t)c * NN + (size_t)blockIdx.y * 128 * NDIM;
    const float* Bg = g_b + (size_t)c * NN + (size_t)blockIdx.x * 128 * NDIM;
    float* Cg = g_t + (size_t)c * NN + (size_t)blockIdx.y * 128 * NDIM + (size_t)blockIdx.x * 128;

    float acc[8][8];
    #pragma unroll
    for (int r = 0; r < 8; r++)
        #pragma unroll
        for (int j = 0; j < 8; j++) acc[r][j] = 0.f;

    const int q = t & 7;        // float4 index along k
    const int rb = t >> 3;      // row base 0..31

    for (int kc = 0; kc < 24; kc++) {
        __syncthreads();
        #pragma unroll
        for (int i = 0; i < 4; i++) {
            int row = i * 32 + rb;
            float4 va = *(const float4*)(Ag + (size_t)row * NDIM + kc * 32 + q * 4);
            float4 vb = *(const float4*)(Bg + (size_t)row * NDIM + kc * 32 + q * 4);
            As[q * 4 + 0][row] = va.x; As[q * 4 + 1][row] = va.y;
            As[q * 4 + 2][row] = va.z; As[q * 4 + 3][row] = va.w;
            Bs[q * 4 + 0][row] = vb.x; Bs[q * 4 + 1][row] = vb.y;
            Bs[q * 4 + 2][row] = vb.z; Bs[q * 4 + 3][row] = vb.w;
        }
        __syncthreads();

        #pragma unroll
        for (int kk = 0; kk < 32; kk++) {
            float a[8], b[8];
            *(float4*)&a[0] = *(const float4*)&As[kk][ty * 8];
            *(float4*)&a[4] = *(const float4*)&As[kk][ty * 8 + 4];
            *(float4*)&b[0] = *(const float4*)&Bs[kk][tx * 8];
            *(float4*)&b[4] = *(const float4*)&Bs[kk][tx * 8 + 4];
            #pragma unroll
            for (int r = 0; r < 8; r++)
                #pragma unroll
                for (int j = 0; j < 8; j++)
                    acc[r][j] += a[r] * b[j];
        }
    }

    #pragma unroll
    for (int r = 0; r < 8; r++) {
        float4 v0 = make_float4(acc[r][0], acc[r][1], acc[r][2], acc[r][3]);
        float4 v1 = make_float4(acc[r][4], acc[r][5], acc[r][6], acc[r][7]);
        float* dst = Cg + (size_t)(ty * 8 + r) * NDIM + tx * 8;
        *(float4*)dst = v0;
        *(float4*)(dst + 4) = v1;
    }
}

// ---------------------------------------------------------------------------
// Kernel C: LN2 + (@ out_w.T) + gating multiply. Block: 64 pixels.
// ---------------------------------------------------------------------------
__global__ __launch_bounds__(256) void kC(
    const float* __restrict__ ln2w, const float* __restrict__ ln2b,
    const float* __restrict__ outw, float* __restrict__ out)
{
    __shared__ float Cs[128][65];   // [channel][pixel], padded
    __shared__ float Wc[16][128];   // c-chunk x 128 outputs

    const int t = threadIdx.x;
    const size_t P0 = (size_t)blockIdx.x * 64;

    // Load tmp tile: Cs[c][p] = g_t[c][P0+p] (coalesced per channel)
    #pragma unroll
    for (int i = 0; i < 32; i++) {
        int e = i * 256 + t;
        int cc = e >> 6, p = e & 63;
        Cs[cc][p] = g_t[(size_t)cc * NN + P0 + p];
    }
    __syncthreads();

    // LN over channels, 4 threads per pixel
    {
        const int p = t >> 2, quad = t & 3;
        const int c0 = quad * 32;
        float s = 0.f;
        #pragma unroll
        for (int k = 0; k < 32; k++) s += Cs[c0 + k][p];
        s += __shfl_xor_sync(0xffffffffu, s, 1);
        s += __shfl_xor_sync(0xffffffffu, s, 2);
        const float mu = s * (1.0f / 128.0f);
        float vv = 0.f;
        #pragma unroll
        for (int k = 0; k < 32; k++) { float d = Cs[c0 + k][p] - mu; vv += d * d; }
        vv += __shfl_xor_sync(0xffffffffu, vv, 1);
        vv += __shfl_xor_sync(0xffffffffu, vv, 2);
        const float inv = rsqrtf(vv * (1.0f / 128.0f) + 1e-5f);
        #pragma unroll
        for (int k = 0; k < 32; k++) {
            int cc = c0 + k;
            Cs[cc][p] = (Cs[cc][p] - mu) * inv * ln2w[cc] + ln2b[cc];
        }
    }
    __syncthreads();

    const int tx = t & 15, ty = t >> 4;
    float acc[4][8];
    #pragma unroll
    for (int r = 0; r < 4; r++)
        #pragma unroll
        for (int j = 0; j < 8; j++) acc[r][j] = 0.f;

    for (int cc0 = 0; cc0 < 128; cc0 += 16) {
        __syncthreads();
        #pragma unroll
        for (int i = 0; i < 2; i++) {
            int e = i * 256 + t;        // 512 float4s total
            int o = e >> 2, qq = e & 3;
            float4 v = *(const float4*)(outw + (size_t)o * CDIM + cc0 + qq * 4);
            Wc[qq * 4 + 0][o] = v.x; Wc[qq * 4 + 1][o] = v.y;
            Wc[qq * 4 + 2][o] = v.z; Wc[qq * 4 + 3][o] = v.w;
        }
        __syncthreads();

        #pragma unroll
        for (int kk = 0; kk < 16; kk++) {
            float xv[4];
            #pragma unroll
            for (int r = 0; r < 4; r++) xv[r] = Cs[cc0 + kk][ty * 4 + r];
            float wv[8];
            *(float4*)&wv[0] = *(const float4*)&Wc[kk][tx * 8];
            *(float4*)&wv[4] = *(const float4*)&Wc[kk][tx * 8 + 4];
            #pragma unroll
            for (int r = 0; r < 4; r++)
                #pragma unroll
                for (int j = 0; j < 8; j++)
                    acc[r][j] += xv[r] * wv[j];
        }
    }

    #pragma unroll
    for (int r = 0; r < 4; r++) {
        size_t P = P0 + (size_t)(ty * 4 + r);
        const float* gp = g_g + P * CDIM + tx * 8;
        float* op = out + P * CDIM + tx * 8;
        float4 g0 = *(const float4*)gp;
        float4 g1 = *(const float4*)(gp + 4);
        float4 o0 = make_float4(acc[r][0] * g0.x, acc[r][1] * g0.y,
                                acc[r][2] * g0.z, acc[r][3] * g0.w);
        float4 o1 = make_float4(acc[r][4] * g1.x, acc[r][5] * g1.y,
                                acc[r][6] * g1.z, acc[r][7] * g1.w);
        *(float4*)op = o0;
        *(float4*)(op + 4) = o1;
    }
}

extern "C" void kernel_launch(void* const* d_in, const int* in_sizes, int n_in,
                              void* d_out, int out_size)
{
    const float* pair    = (const float*)d_in[0];
    const float* mask    = (const float*)d_in[1];
    const float* ln1w    = (const float*)d_in[2];
    const float* ln1b    = (const float*)d_in[3];
    const float* projw   = (const float*)d_in[4];
    const float* gatew   = (const float*)d_in[5];
    const float* ln2w    = (const float*)d_in[6];
    const float* ln2b    = (const float*)d_in[7];
    const float* outw    = (const float*)d_in[8];
    const float* gatingw = (const float*)d_in[9];
    float* out = (float*)d_out;

    kA<<<dim3(9216, 8), 256>>>(pair, mask, ln1w, ln1b, projw, gatew, gatingw);
    kB<<<dim3(6, 6, 128), 256>>>();
    kC<<<9216, 256>>>(ln2w, ln2b, outw, out);
}

// round 5
// speedup vs baseline: 1.2341x; 1.2341x over previous
#include <cuda_runtime.h>
#include <cuda_bf16.h>
#include <cstdint>
#include <cstddef>

#define NDIM 768
#define CDIM 128
#define NN ((size_t)NDIM * (size_t)NDIM)

// Scratch (__device__ globals; allocation-free rule).
//   g_a_hi/lo, g_b_hi/lo : (C, N, N) bf16 hi/lo split (NT GEMM operands, k contiguous)
//   g_g : (N*N, C) fp32  sigmoid(x @ gating_w.T)
//   g_t : (C, N, N) fp32 einsum result
__device__ unsigned short g_a_hi[(size_t)CDIM * NN];
__device__ unsigned short g_a_lo[(size_t)CDIM * NN];
__device__ unsigned short g_b_hi[(size_t)CDIM * NN];
__device__ unsigned short g_b_lo[(size_t)CDIM * NN];
__device__ float g_g[(size_t)NN * CDIM];
__device__ float g_t[(size_t)CDIM * NN];

__device__ __forceinline__ float sigf(float x) { return 1.0f / (1.0f + __expf(-x)); }

__device__ __forceinline__ uint32_t smem_u32(const void* p) {
    uint32_t a;
    asm("{ .reg .u64 t; cvta.to.shared.u64 t, %1; cvt.u32.u64 %0, t; }" : "=r"(a) : "l"(p));
    return a;
}

// Baseline-ISA tensor ops (sm_80+; valid on .target sm_103).
__device__ __forceinline__ void ldm_x4(uint32_t (&r)[4], uint32_t addr) {
    asm volatile("ldmatrix.sync.aligned.m8n8.x4.shared.b16 {%0,%1,%2,%3}, [%4];"
        : "=r"(r[0]), "=r"(r[1]), "=r"(r[2]), "=r"(r[3]) : "r"(addr));
}
__device__ __forceinline__ void ldm_x2(uint32_t (&r)[2], uint32_t addr) {
    asm volatile("ldmatrix.sync.aligned.m8n8.x2.shared.b16 {%0,%1}, [%2];"
        : "=r"(r[0]), "=r"(r[1]) : "r"(addr));
}
__device__ __forceinline__ void mma16816(float (&d)[4], const uint32_t (&a)[4],
                                         const uint32_t (&b)[2]) {
    asm volatile("mma.sync.aligned.m16n8k16.row.col.f32.bf16.bf16.f32 "
                 "{%0,%1,%2,%3}, {%4,%5,%6,%7}, {%8,%9}, {%0,%1,%2,%3};"
        : "+f"(d[0]), "+f"(d[1]), "+f"(d[2]), "+f"(d[3])
        : "r"(a[0]), "r"(a[1]), "r"(a[2]), "r"(a[3]), "r"(b[0]), "r"(b[1]));
}

// ---------------------------------------------------------------------------
// Kernel A: LN1 + [proj|gate|gating] GEMM + sigmoid/mask epilogue -> bf16 hi/lo.
// Block: 64 pixels x 16 channels. Staged SMEM writeout for coalesced stores.
// ---------------------------------------------------------------------------
__global__ __launch_bounds__(256) void kA(
    const float* __restrict__ pair, const float* __restrict__ mask,
    const float* __restrict__ ln1w, const float* __restrict__ ln1b,
    const float* __restrict__ projw, const float* __restrict__ gatew,
    const float* __restrict__ gatingw)
{
    __shared__ __align__(16) float Xs[64][132];
    __shared__ __align__(16) float Ws[32][81];

    const int t = threadIdx.x;
    const size_t P0 = (size_t)blockIdx.x * 64;
    const float* src = pair + P0 * CDIM;

    #pragma unroll
    for (int i = 0; i < 8; i++) {
        int idx = i * 1024 + t * 4;
        int p = idx >> 7, k = idx & 127;
        float4 v = *(const float4*)(src + idx);
        *(float4*)&Xs[p][k] = v;
    }
    __syncthreads();

    {   // LayerNorm: 4 threads per pixel row
        const int row = t >> 2, quad = t & 3;
        const int k0 = quad * 32;
        float s = 0.f;
        #pragma unroll
        for (int k = 0; k < 32; k++) s += Xs[row][k0 + k];
        s += __shfl_xor_sync(0xffffffffu, s, 1);
        s += __shfl_xor_sync(0xffffffffu, s, 2);
        const float mu = s * (1.0f / 128.0f);
        float vv = 0.f;
        #pragma unroll
        for (int k = 0; k < 32; k++) { float d = Xs[row][k0 + k] - mu; vv += d * d; }
        vv += __shfl_xor_sync(0xffffffffu, vv, 1);
        vv += __shfl_xor_sync(0xffffffffu, vv, 2);
        const float inv = rsqrtf(vv * (1.0f / 128.0f) + 1e-5f);
        #pragma unroll
        for (int k = 0; k < 32; k++) {
            int kk = k0 + k;
            Xs[row][kk] = (Xs[row][kk] - mu) * inv * ln1w[kk] + ln1b[kk];
        }
    }
    __syncthreads();

    const int tx = t & 15;
    const int ty = t >> 4;
    const int cbase = blockIdx.y * 16;
    const int wid = t >> 5, lane = t & 31;

    float acc[4][5];
    #pragma unroll
    for (int r = 0; r < 4; r++)
        #pragma unroll
        for (int j = 0; j < 5; j++) acc[r][j] = 0.f;

    for (int kc = 0; kc < 4; kc++) {
        __syncthreads();
        #pragma unroll
        for (int i = 0; i < 10; i++) {
            int o = i * 8 + wid;
            int cl = o / 5, r = o % 5;
            int c = cbase + cl;
            const float* rp;
            if (r == 0)      rp = projw   + (size_t)(2 * c) * CDIM;
            else if (r == 1) rp = gatew   + (size_t)(2 * c) * CDIM;
            else if (r == 2) rp = projw   + (size_t)(2 * c + 1) * CDIM;
            else if (r == 3) rp = gatew   + (size_t)(2 * c + 1) * CDIM;
            else             rp = gatingw + (size_t)c * CDIM;
            Ws[lane][o] = rp[kc * 32 + lane];
        }
        __syncthreads();

        #pragma unroll
        for (int kk = 0; kk < 32; kk++) {
            const int k = kc * 32 + kk;
            float xv[4];
            #pragma unroll
            for (int r = 0; r < 4; r++) xv[r] = Xs[ty * 4 + r][k];
            float wv[5];
            #pragma unroll
            for (int j = 0; j < 5; j++) wv[j] = Ws[kk][tx * 5 + j];
            #pragma unroll
            for (int r = 0; r < 4; r++)
                #pragma unroll
                for (int j = 0; j < 5; j++)
                    acc[r][j] += xv[r] * wv[j];
        }
    }

    // Epilogue: stage to SMEM (reusing Ws/Xs), then coalesced global writes.
    __syncthreads();
    uint16_t* Sst = (uint16_t*)&Ws[0][0];  // 4 arrays x 16 ch x 64 px, stride 68
    float* Sg = &Xs[0][0];                 // 64 px x 16 ch, stride 17

    #pragma unroll
    for (int r = 0; r < 4; r++) {
        int p = ty * 4 + r;
        size_t P = P0 + (size_t)p;
        float m = mask[(int)(P % NDIM)];
        float av = acc[r][0] * sigf(acc[r][1]) * m;
        float bv = acc[r][2] * sigf(acc[r][3]) * m;
        float gv = sigf(acc[r][4]);
        __nv_bfloat16 ah = __float2bfloat16_rn(av);
        __nv_bfloat16 al = __float2bfloat16_rn(av - __bfloat162float(ah));
        __nv_bfloat16 bh = __float2bfloat16_rn(bv);
        __nv_bfloat16 bl = __float2bfloat16_rn(bv - __bfloat162float(bh));
        Sst[0 * 1088 + tx * 68 + p] = __bfloat16_as_ushort(ah);
        Sst[1 * 1088 + tx * 68 + p] = __bfloat16_as_ushort(al);
        Sst[2 * 1088 + tx * 68 + p] = __bfloat16_as_ushort(bh);
        Sst[3 * 1088 + tx * 68 + p] = __bfloat16_as_ushort(bl);
        Sg[p * 17 + tx] = gv;
    }
    __syncthreads();

    {
        int row = t >> 4, col = t & 15;
        size_t gbase = (size_t)(cbase + row) * NN + P0 + (size_t)col * 4;
        uint2 v;
        v = *(const uint2*)(Sst + 0 * 1088 + row * 68 + col * 4); *(uint2*)(g_a_hi + gbase) = v;
        v = *(const uint2*)(Sst + 1 * 1088 + row * 68 + col * 4); *(uint2*)(g_a_lo + gbase) = v;
        v = *(const uint2*)(Sst + 2 * 1088 + row * 68 + col * 4); *(uint2*)(g_b_hi + gbase) = v;
        v = *(const uint2*)(Sst + 3 * 1088 + row * 68 + col * 4); *(uint2*)(g_b_lo + gbase) = v;
        #pragma unroll
        for (int i = 0; i < 4; i++) {
            int e = i * 256 + t;
            int p = e >> 4, cc = e & 15;
            g_g[(P0 + p) * CDIM + cbase + cc] = Sg[p * 17 + cc];
        }
    }
}

// ---------------------------------------------------------------------------
// Kernel B (mma.sync bf16 hi/lo x3 emulated-fp32): batched NT GEMM.
// Per CTA: 128x128 tile for one channel; 8 warps (2x4), warp tile 64x32.
// K=768 in 12 chunks of 64; cp.async double-buffered SMEM (rows padded 144B).
// ---------------------------------------------------------------------------
#define KB_STRIDE 144                     // bytes per padded row (72 bf16)
#define KB_ARR    18432                   // 128 rows * 144B per operand array
#define KB_STAGE  (4 * KB_ARR)            // Ahi Alo Bhi Blo = 73728
#define KB_SMEM   (2 * KB_STAGE)          // 147456

__global__ __launch_bounds__(256, 1) void kB_mma()
{
    extern __shared__ __align__(16) char sm[];
    const uint32_t sb = smem_u32(sm);
    const int t = threadIdx.x, lane = t & 31, wid = t >> 5;
    const int wm = wid >> 2, wn = wid & 3;          // 2 x 4 warp grid
    const int c = blockIdx.z;
    const size_t i0 = (size_t)blockIdx.y * 128, j0 = (size_t)blockIdx.x * 128;

    const unsigned short* pA_hi = g_a_hi + (size_t)c * NN + i0 * NDIM;
    const unsigned short* pA_lo = g_a_lo + (size_t)c * NN + i0 * NDIM;
    const unsigned short* pB_hi = g_b_hi + (size_t)c * NN + j0 * NDIM;
    const unsigned short* pB_lo = g_b_lo + (size_t)c * NN + j0 * NDIM;

    const int seg = t & 7, r0 = t >> 3;             // 8 segs x 32 rows

#define ISSUE_LOADS(chunk_) do { \
    int _k0 = (chunk_) * 64; \
    uint32_t _tb = sb + ((chunk_) & 1) * KB_STAGE; \
    _Pragma("unroll") \
    for (int _rr = 0; _rr < 4; _rr++) { \
        int _row = _rr * 32 + r0; \
        uint32_t _s = _row * KB_STRIDE + seg * 16; \
        size_t _g = (size_t)_row * NDIM + _k0 + seg * 8; \
        asm volatile("cp.async.cg.shared.global [%0], [%1], 16;" :: "r"(_tb + 0 * KB_ARR + _s), "l"(pA_hi + _g)); \
        asm volatile("cp.async.cg.shared.global [%0], [%1], 16;" :: "r"(_tb + 1 * KB_ARR + _s), "l"(pA_lo + _g)); \
        asm volatile("cp.async.cg.shared.global [%0], [%1], 16;" :: "r"(_tb + 2 * KB_ARR + _s), "l"(pB_hi + _g)); \
        asm volatile("cp.async.cg.shared.global [%0], [%1], 16;" :: "r"(_tb + 3 * KB_ARR + _s), "l"(pB_lo + _g)); \
    } } while (0)

    float acc[4][4][4];
    #pragma unroll
    for (int mt = 0; mt < 4; mt++)
        #pragma unroll
        for (int nt = 0; nt < 4; nt++)
            #pragma unroll
            for (int r = 0; r < 4; r++) acc[mt][nt][r] = 0.f;

    ISSUE_LOADS(0);
    asm volatile("cp.async.commit_group;" ::: "memory");

    // ldmatrix per-lane address components (canonical m16n8k16 fragment layout):
    // A .x4: lane groups 0-7/8-15/16-23/24-31 -> (rows m0..+7 | m0+8..+15) x (k0-7 | k8-15)
    const int a_row_l = (lane & 7) + 8 * ((lane >> 3) & 1);
    const int a_koff  = 16 * (lane >> 4);           // bytes: +8 bf16 for lanes 16-31
    // B .x2: lanes 0-7 -> rows n0..+7 @ k0-7 ; lanes 8-15 -> rows n0..+7 @ k8-15
    const int b_row_l = lane & 7;
    const int b_koff  = 16 * ((lane >> 3) & 1);

    for (int chunk = 0; chunk < 12; chunk++) {
        if (chunk + 1 < 12) {
            ISSUE_LOADS(chunk + 1);
            asm volatile("cp.async.commit_group;" ::: "memory");
            asm volatile("cp.async.wait_group 1;" ::: "memory");
        } else {
            asm volatile("cp.async.wait_group 0;" ::: "memory");
        }
        __syncthreads();

        const uint32_t stb = sb + (chunk & 1) * KB_STAGE;
        #pragma unroll
        for (int ks = 0; ks < 4; ks++) {
            const int kb = ks * 32;                  // k-step byte offset (16 bf16)
            uint32_t a_hi[4][4], a_lo[4][4];
            #pragma unroll
            for (int mt = 0; mt < 4; mt++) {
                uint32_t off = (wm * 64 + mt * 16 + a_row_l) * KB_STRIDE + kb + a_koff;
                ldm_x4(a_hi[mt], stb + 0 * KB_ARR + off);
                ldm_x4(a_lo[mt], stb + 1 * KB_ARR + off);
            }
            uint32_t b_hi[4][2], b_lo[4][2];
            #pragma unroll
            for (int nt = 0; nt < 4; nt++) {
                uint32_t off = (wn * 32 + nt * 8 + b_row_l) * KB_STRIDE + kb + b_koff;
                ldm_x2(b_hi[nt], stb + 2 * KB_ARR + off);
                ldm_x2(b_lo[nt], stb + 3 * KB_ARR + off);
            }
            #pragma unroll
            for (int mt = 0; mt < 4; mt++)
                #pragma unroll
                for (int nt = 0; nt < 4; nt++) {
                    mma16816(acc[mt][nt], a_hi[mt], b_hi[nt]);
                    mma16816(acc[mt][nt], a_hi[mt], b_lo[nt]);
                    mma16816(acc[mt][nt], a_lo[mt], b_hi[nt]);
                }
        }
        __syncthreads();
    }

    // Epilogue: acc lane layout -> g_t[c][i][j]
    const size_t crow = (size_t)c * NN;
    #pragma unroll
    for (int mt = 0; mt < 4; mt++) {
        size_t row = i0 + (size_t)(wm * 64 + mt * 16 + (lane >> 2));
        #pragma unroll
        for (int nt = 0; nt < 4; nt++) {
            size_t col = j0 + (size_t)(wn * 32 + nt * 8 + (lane & 3) * 2);
            *(float2*)&g_t[crow + row * NDIM + col] =
                make_float2(acc[mt][nt][0], acc[mt][nt][1]);
            *(float2*)&g_t[crow + (row + 8) * NDIM + col] =
                make_float2(acc[mt][nt][2], acc[mt][nt][3]);
        }
    }
#undef ISSUE_LOADS
}

// ---------------------------------------------------------------------------
// Kernel C: LN2 + (@ out_w.T) + gating multiply. Block: 64 pixels.
// ---------------------------------------------------------------------------
__global__ __launch_bounds__(256) void kC(
    const float* __restrict__ ln2w, const float* __restrict__ ln2b,
    const float* __restrict__ outw, float* __restrict__ out)
{
    __shared__ float Cs[128][65];
    __shared__ float Wc[16][128];

    const int t = threadIdx.x;
    const size_t P0 = (size_t)blockIdx.x * 64;

    #pragma unroll
    for (int i = 0; i < 32; i++) {
        int e = i * 256 + t;
        int cc = e >> 6, p = e & 63;
        Cs[cc][p] = g_t[(size_t)cc * NN + P0 + p];
    }
    __syncthreads();

    {
        const int p = t >> 2, quad = t & 3;
        const int c0 = quad * 32;
        float s = 0.f;
        #pragma unroll
        for (int k = 0; k < 32; k++) s += Cs[c0 + k][p];
        s += __shfl_xor_sync(0xffffffffu, s, 1);
        s += __shfl_xor_sync(0xffffffffu, s, 2);
        const float mu = s * (1.0f / 128.0f);
        float vv = 0.f;
        #pragma unroll
        for (int k = 0; k < 32; k++) { float d = Cs[c0 + k][p] - mu; vv += d * d; }
        vv += __shfl_xor_sync(0xffffffffu, vv, 1);
        vv += __shfl_xor_sync(0xffffffffu, vv, 2);
        const float inv = rsqrtf(vv * (1.0f / 128.0f) + 1e-5f);
        #pragma unroll
        for (int k = 0; k < 32; k++) {
            int cc = c0 + k;
            Cs[cc][p] = (Cs[cc][p] - mu) * inv * ln2w[cc] + ln2b[cc];
        }
    }
    __syncthreads();

    const int tx = t & 15, ty = t >> 4;
    float acc[4][8];
    #pragma unroll
    for (int r = 0; r < 4; r++)
        #pragma unroll
        for (int j = 0; j < 8; j++) acc[r][j] = 0.f;

    for (int cc0 = 0; cc0 < 128; cc0 += 16) {
        __syncthreads();
        #pragma unroll
        for (int i = 0; i < 2; i++) {
            int e = i * 256 + t;
            int o = e >> 2, qq = e & 3;
            float4 v = *(const float4*)(outw + (size_t)o * CDIM + cc0 + qq * 4);
            Wc[qq * 4 + 0][o] = v.x; Wc[qq * 4 + 1][o] = v.y;
            Wc[qq * 4 + 2][o] = v.z; Wc[qq * 4 + 3][o] = v.w;
        }
        __syncthreads();

        #pragma unroll
        for (int kk = 0; kk < 16; kk++) {
            float xv[4];
            #pragma unroll
            for (int r = 0; r < 4; r++) xv[r] = Cs[cc0 + kk][ty * 4 + r];
            float wv[8];
            *(float4*)&wv[0] = *(const float4*)&Wc[kk][tx * 8];
            *(float4*)&wv[4] = *(const float4*)&Wc[kk][tx * 8 + 4];
            #pragma unroll
            for (int r = 0; r < 4; r++)
                #pragma unroll
                for (int j = 0; j < 8; j++)
                    acc[r][j] += xv[r] * wv[j];
        }
    }

    #pragma unroll
    for (int r = 0; r < 4; r++) {
        size_t P = P0 + (size_t)(ty * 4 + r);
        const float* gp = g_g + P * CDIM + tx * 8;
        float* op = out + P * CDIM + tx * 8;
        float4 g0 = *(const float4*)gp;
        float4 g1 = *(const float4*)(gp + 4);
        float4 o0 = make_float4(acc[r][0] * g0.x, acc[r][1] * g0.y,
                                acc[r][2] * g0.z, acc[r][3] * g0.w);
        float4 o1 = make_float4(acc[r][4] * g1.x, acc[r][5] * g1.y,
                                acc[r][6] * g1.z, acc[r][7] * g1.w);
        *(float4*)op = o0;
        *(float4*)(op + 4) = o1;
    }
}

extern "C" void kernel_launch(void* const* d_in, const int* in_sizes, int n_in,
                              void* d_out, int out_size)
{
    const float* pair    = (const float*)d_in[0];
    const float* mask    = (const float*)d_in[1];
    const float* ln1w    = (const float*)d_in[2];
    const float* ln1b    = (const float*)d_in[3];
    const float* projw   = (const float*)d_in[4];
    const float* gatew   = (const float*)d_in[5];
    const float* ln2w    = (const float*)d_in[6];
    const float* ln2b    = (const float*)d_in[7];
    const float* outw    = (const float*)d_in[8];
    const float* gatingw = (const float*)d_in[9];
    float* out = (float*)d_out;

    static int attr_set = 0;
    if (!attr_set) {
        cudaFuncSetAttribute(kB_mma, cudaFuncAttributeMaxDynamicSharedMemorySize, KB_SMEM);
        attr_set = 1;
    }

    kA<<<dim3(9216, 8), 256>>>(pair, mask, ln1w, ln1b, projw, gatew, gatingw);
    kB_mma<<<dim3(6, 6, 128), 256, KB_SMEM>>>();
    kC<<<9216, 256>>>(ln2w, ln2b, outw, out);
}